// round 9
// baseline (speedup 1.0000x reference)
#include <cuda_runtime.h>
#include <cstdint>

#define K_NEIGH 20
#define THRES 0.5f
#define WPB 8
#define LCAP 16
#define PIVOT 0.02f

// One warp per row of the (B*N, N) fp32 distance matrix.
// Key = ((float_bits(x)+1) << 32) | col  -> unique; ascending key order ==
// (value asc, col asc) == jax.lax.top_k(-x, 20) stable output order.
//
// Fast path: per-lane register candidate filter (x < PIVOT), then 20 rounds of
// warp-min with an exclusive lower bound. Exact full-row fallback when any lane
// overflows or the row has < K_NEIGH candidates -> correct for ANY input.
//
// OUTPUT IS float32: harness __output__ dtype is f32 (indices canonicalized);
// indices < 4096 are exactly representable.

__device__ __forceinline__ unsigned long long warp_min_u64(unsigned long long m) {
    #pragma unroll
    for (int off = 16; off > 0; off >>= 1) {
        unsigned long long o = __shfl_xor_sync(0xFFFFFFFFu, m, off);
        if (o < m) m = o;
    }
    return m;
}

__global__ void __launch_bounds__(WPB * 32)
knn_thres_kernel(const float* __restrict__ x, float* __restrict__ out,
                 int N, int rows) {
    const int warp = threadIdx.x >> 5;
    const int lane = threadIdx.x & 31;
    const int row  = blockIdx.x * WPB + warp;
    if (row >= rows) return;

    const float* __restrict__ xrow = x + (size_t)row * (size_t)N;

    // ---- Phase 1: pivot filter into per-lane register candidates ----
    unsigned long long loc[LCAP];
    int cl = 0;

    const int nvec = N >> 2;
    const float4* __restrict__ xv = (const float4*)xrow;
    for (int i = lane; i < nvec; i += 32) {
        float4 v = xv[i];
        const int base = i << 2;
        float vs[4] = {v.x, v.y, v.z, v.w};
        #pragma unroll
        for (int j = 0; j < 4; j++) {
            if (vs[j] < PIVOT) {
                if (cl < LCAP) {
                    unsigned int bits = __float_as_uint(vs[j]) + 1u;
                    loc[cl] = ((unsigned long long)bits << 32)
                              | (unsigned int)(base + j);
                }
                cl++;
            }
        }
    }
    // scalar tail (N % 4 != 0; not hit for N = 4096)
    for (int i = (nvec << 2) + lane; i < N; i += 32) {
        float v = xrow[i];
        if (v < PIVOT) {
            if (cl < LCAP) {
                unsigned int bits = __float_as_uint(v) + 1u;
                loc[cl] = ((unsigned long long)bits << 32) | (unsigned int)i;
            }
            cl++;
        }
    }

    // warp-uniform fast/fallback decision
    const unsigned ovf = __ballot_sync(0xFFFFFFFFu, cl > LCAP);
    int tot = cl;
    #pragma unroll
    for (int off = 16; off > 0; off >>= 1)
        tot += __shfl_xor_sync(0xFFFFFFFFu, tot, off);
    const bool fast = (ovf == 0u) && (tot >= K_NEIGH);

    const float self_idx = (float)(row % N);       // row index within its batch
    float* __restrict__ orow = out + (size_t)row * K_NEIGH;
    unsigned long long prev = 0ULL;                // all keys > 0 (bits+1 >= 1)

    if (fast) {
        const int cn = cl;                         // cl <= LCAP here
        for (int sel = 0; sel < K_NEIGH; sel++) {
            unsigned long long m = ~0ULL;
            #pragma unroll 4
            for (int s = 0; s < cn; s++) {
                unsigned long long k = loc[s];
                if (k > prev && k < m) m = k;
            }
            m = warp_min_u64(m);
            prev = m;
            if (lane == 0) {
                unsigned int bits = (unsigned int)(m >> 32) - 1u;
                float val = __uint_as_float(bits);
                float idx = (float)(unsigned int)(m & 0xFFFFFFFFu);
                orow[sel] = (val > THRES) ? self_idx : idx;
            }
        }
    } else {
        // ---- Exact fallback over the full row (correct for ANY input) ----
        for (int sel = 0; sel < K_NEIGH; sel++) {
            unsigned long long m = ~0ULL;
            for (int i = lane; i < N; i += 32) {
                unsigned int bits = __float_as_uint(xrow[i]) + 1u;
                unsigned long long k =
                    ((unsigned long long)bits << 32) | (unsigned int)i;
                if (k > prev && k < m) m = k;
            }
            m = warp_min_u64(m);
            prev = m;
            if (lane == 0) {
                unsigned int bits = (unsigned int)(m >> 32) - 1u;
                float val = __uint_as_float(bits);
                float idx = (float)(unsigned int)(m & 0xFFFFFFFFu);
                orow[sel] = (val > THRES) ? self_idx : idx;
            }
        }
    }
}

extern "C" void kernel_launch(void* const* d_in, const int* in_sizes, int n_in,
                              void* d_out, int out_size) {
    // the distance matrix is by far the largest input
    int xi = 0;
    for (int i = 1; i < n_in; i++)
        if (in_sizes[i] > in_sizes[xi]) xi = i;

    const float* x = (const float*)d_in[xi];
    float* out = (float*)d_out;

    const int rows = out_size / K_NEIGH;           // B * N  (= 65536 expected)
    const int N    = in_sizes[xi] / rows;          // num points (= 4096 expected)

    const int blocks = (rows + WPB - 1) / WPB;
    knn_thres_kernel<<<blocks, WPB * 32>>>(x, out, N, rows);
}

// round 10
// speedup vs baseline: 1.3350x; 1.3350x over previous
#include <cuda_runtime.h>
#include <cstdint>

#define K_NEIGH 20
#define THRES 0.5f
#define WPB 8
#define LCAP 16
#define SCAP 128
#define PIVOT 0.012f

// One warp per row of the (B*N, N) fp32 distance matrix. Output dtype f32.
//
// Key = ((float_bits(x)+1) << 32) | col : unique; ascending key order ==
// (value asc, col asc) == jax.lax.top_k(-x, 20) stable output order.
//
// Fast path:
//   1) screened filter: FMIN-tree over 16 elements, only inspect groups
//      containing a value < PIVOT  (E[candidates/row] ~ 49 at PIVOT=0.012)
//   2) warp-scan compaction of per-lane candidates into shared memory
//   3) rank selection: each candidate counts smaller keys (one broadcast
//      sweep over shared); rank < 20 scatters directly to out[rank].
// Fallback (exact, any input): 20 rounds of bounded (value,index) warp-min
// over the full row — taken on lane overflow or C < 20 or C > SCAP.

__device__ __forceinline__ unsigned long long warp_min_u64(unsigned long long m) {
    #pragma unroll
    for (int off = 16; off > 0; off >>= 1) {
        unsigned long long o = __shfl_xor_sync(0xFFFFFFFFu, m, off);
        if (o < m) m = o;
    }
    return m;
}

__global__ void __launch_bounds__(WPB * 32)
knn_thres_kernel(const float* __restrict__ x, float* __restrict__ out,
                 int N, int rows) {
    __shared__ unsigned long long cand[WPB][SCAP];

    const int warp = threadIdx.x >> 5;
    const int lane = threadIdx.x & 31;
    const int row  = blockIdx.x * WPB + warp;
    if (row >= rows) return;

    const float* __restrict__ xrow = x + (size_t)row * (size_t)N;

    unsigned long long loc[LCAP];
    int cl = 0;

    const int nvec = N >> 2;
    const float4* __restrict__ xv = (const float4*)xrow;

    // push all elements of one float4 that pass the pivot (vector pre-screened)
    auto push4 = [&](float4 v, int vecidx, float mv) {
        if (mv < PIVOT) {
            float vs[4] = {v.x, v.y, v.z, v.w};
            const int base = vecidx << 2;
            #pragma unroll
            for (int j = 0; j < 4; j++) {
                if (vs[j] < PIVOT) {
                    if (cl < LCAP) {
                        unsigned int bits = __float_as_uint(vs[j]) + 1u;
                        loc[cl] = ((unsigned long long)bits << 32)
                                  | (unsigned int)(base + j);
                    }
                    cl++;
                }
            }
        }
    };

    // ---- Phase 1: screened filter, 16 elements (4 vectors) per check ----
    const int ngroups = nvec >> 7;             // 4 vectors x 32 lanes per group
    for (int g = 0; g < ngroups; g++) {
        const int i = lane + (g << 7);
        float4 a = xv[i];
        float4 b = xv[i + 32];
        float4 c = xv[i + 64];
        float4 d = xv[i + 96];
        float ma = fminf(fminf(a.x, a.y), fminf(a.z, a.w));
        float mb = fminf(fminf(b.x, b.y), fminf(b.z, b.w));
        float mc = fminf(fminf(c.x, c.y), fminf(c.z, c.w));
        float md = fminf(fminf(d.x, d.y), fminf(d.z, d.w));
        if (fminf(fminf(ma, mb), fminf(mc, md)) < PIVOT) {
            push4(a, i, ma);
            push4(b, i + 32, mb);
            push4(c, i + 64, mc);
            push4(d, i + 96, md);
        }
    }
    // remainder vectors (nvec % 128 != 0; not hit for N = 4096)
    for (int i = lane + (ngroups << 7); i < nvec; i += 32) {
        float4 v = xv[i];
        float mv = fminf(fminf(v.x, v.y), fminf(v.z, v.w));
        push4(v, i, mv);
    }
    // scalar tail (N % 4 != 0; not hit for N = 4096)
    for (int i = (nvec << 2) + lane; i < N; i += 32) {
        float v = xrow[i];
        if (v < PIVOT) {
            if (cl < LCAP) {
                unsigned int bits = __float_as_uint(v) + 1u;
                loc[cl] = ((unsigned long long)bits << 32) | (unsigned int)i;
            }
            cl++;
        }
    }

    // ---- warp scan: overflow check, total, exclusive offsets ----
    const unsigned ovf = __ballot_sync(0xFFFFFFFFu, cl > LCAP);
    int incl = cl;
    #pragma unroll
    for (int off = 1; off < 32; off <<= 1) {
        int o = __shfl_up_sync(0xFFFFFFFFu, incl, off);
        if (lane >= off) incl += o;
    }
    const int tot  = __shfl_sync(0xFFFFFFFFu, incl, 31);
    const int offs = incl - cl;
    const bool fast = (ovf == 0u) && (tot >= K_NEIGH) && (tot <= SCAP);

    const float self_idx = (float)(row % N);        // row index within batch
    float* __restrict__ orow = out + (size_t)row * K_NEIGH;

    if (fast) {
        // ---- Phase 2: compact into shared ----
        for (int t = 0; t < cl; t++)
            cand[warp][offs + t] = loc[t];
        __syncwarp();

        // ---- Phase 3: rank selection, direct scatter ----
        const int C = tot;
        const unsigned long long* __restrict__ cw = cand[warp];
        for (int s = lane; s < C; s += 32) {
            const unsigned long long k = cw[s];
            int rank = 0;
            #pragma unroll 4
            for (int j = 0; j < C; j++)
                rank += (cw[j] < k);
            if (rank < K_NEIGH) {
                unsigned int bits = (unsigned int)(k >> 32) - 1u;
                float val = __uint_as_float(bits);
                float idx = (float)(unsigned int)(k & 0xFFFFFFFFu);
                orow[rank] = (val > THRES) ? self_idx : idx;
            }
        }
    } else {
        // ---- Exact fallback: 20 bounded warp-min rounds over full row ----
        unsigned long long prev = 0ULL;             // all keys > 0 (bits+1)
        for (int sel = 0; sel < K_NEIGH; sel++) {
            unsigned long long m = ~0ULL;
            for (int i = lane; i < N; i += 32) {
                unsigned int bits = __float_as_uint(xrow[i]) + 1u;
                unsigned long long k =
                    ((unsigned long long)bits << 32) | (unsigned int)i;
                if (k > prev && k < m) m = k;
            }
            m = warp_min_u64(m);
            prev = m;
            if (lane == 0) {
                unsigned int bits = (unsigned int)(m >> 32) - 1u;
                float val = __uint_as_float(bits);
                float idx = (float)(unsigned int)(m & 0xFFFFFFFFu);
                orow[sel] = (val > THRES) ? self_idx : idx;
            }
        }
    }
}

extern "C" void kernel_launch(void* const* d_in, const int* in_sizes, int n_in,
                              void* d_out, int out_size) {
    // the distance matrix is by far the largest input
    int xi = 0;
    for (int i = 1; i < n_in; i++)
        if (in_sizes[i] > in_sizes[xi]) xi = i;

    const float* x = (const float*)d_in[xi];
    float* out = (float*)d_out;

    const int rows = out_size / K_NEIGH;            // B * N  (= 65536 expected)
    const int N    = in_sizes[xi] / rows;           // num points (= 4096 expected)

    const int blocks = (rows + WPB - 1) / WPB;
    knn_thres_kernel<<<blocks, WPB * 32>>>(x, out, N, rows);
}